// round 9
// baseline (speedup 1.0000x reference)
#include <cuda_runtime.h>
#include <cstdint>

// CRF negative log-likelihood, B=256, T=2048, D=64.
// Single fused kernel, 256 threads/CTA, one CTA per batch:
//   warps 0-3: linear-space forward recursion (serial chain), named barrier 1.
//     - packed fma.rn.f32x2 matvec (16 FFMA2/thread/step, halves FMA pressure)
//     - renorm sum S computed during k==7 matvec from loaded u (no pv tree),
//       scale folded into precomputed exs[0] at next block start (off chain)
//     - 8-deep register prefetch of p, exps hoisted per 8-block
//   warps 4-7: length L, emission s1, transition s2 (named barrier 2),
//     overlapping the latency-bound recursion. Combined in epilogue.

#define TT 2048
#define DD 64

typedef unsigned long long ull;

#define FMA2(d,a,b,c)  asm("fma.rn.f32x2 %0, %1, %2, %3;" : "=l"(d) : "l"(a), "l"(b), "l"(c))
#define ADD2(d,a,b)    asm("add.rn.f32x2 %0, %1, %2;"     : "=l"(d) : "l"(a), "l"(b))
#define PACK2(d,lo,hi) asm("mov.b64 %0, {%1, %2};"        : "=l"(d) : "f"(lo), "f"(hi))
#define UNPACK2(lo,hi,v) asm("mov.b64 {%0, %1}, %2;"      : "=f"(lo), "=f"(hi) : "l"(v))
#define BAR1() asm volatile("bar.sync 1, 128;" ::: "memory")
#define BAR2() asm volatile("bar.sync 2, 128;" ::: "memory")

__global__ __launch_bounds__(256, 2)
void crf_fused(const float* __restrict__ p,
               const int*   __restrict__ y,
               const int*   __restrict__ mask,
               const float* __restrict__ trans,
               float*       __restrict__ out)
{
    const int b   = blockIdx.x;
    const int tid = threadIdx.x;
    const int w   = tid >> 5;
    const int l   = tid & 31;
    const int h   = l >> 4;               // i-half (recursion warps)
    const int j   = ((w & 3) << 4) | (l & 15);  // state (recursion warps)

    __shared__ __align__(16) float ubuf[2][DD];
    __shared__ short lab[TT];
    __shared__ float sred[4];
    __shared__ int   ired[4];

    ull col2[16];

    if (tid >= 128) {
        // ---- length partials ----
        const int4* mb4 = reinterpret_cast<const int4*>(mask + (size_t)b * TT);
        const int idx = tid - 128;
        int msum = 0;
        #pragma unroll
        for (int k2 = 0; k2 < 4; k2++) {
            int4 v = mb4[idx + 128 * k2];
            msum += v.x + v.y + v.z + v.w;
        }
        #pragma unroll
        for (int s = 16; s >= 1; s >>= 1) msum += __shfl_xor_sync(0xffffffffu, msum, s);
        if (l == 0) ired[w - 4] = msum;
    } else {
        // ---- expT half-column, packed into f32x2 pairs ----
        #pragma unroll
        for (int k2 = 0; k2 < 16; k2++) {
            float c0 = __expf(trans[(h * 32 + 2 * k2)     * DD + j]);
            float c1 = __expf(trans[(h * 32 + 2 * k2 + 1) * DD + j]);
            PACK2(col2[k2], c0, c1);
        }
    }
    __syncthreads();
    const int L = TT - (ired[0] + ired[1] + ired[2] + ired[3]);

    float logz = 0.f;

    if (tid >= 128) {
        // =========== scoring warps: labels, s1, s2 ===========
        const int idx = tid - 128;
        const int4* yb4 = reinterpret_cast<const int4*>(y + (size_t)b * TT * DD);
        for (int t = idx; t < TT; t += 128) {
            const int4* row = yb4 + (size_t)t * 16;
            int lv = 0;
            #pragma unroll
            for (int k2 = 0; k2 < 16; k2++) {
                int4 v = row[k2];
                lv += v.x * (4 * k2) + v.y * (4 * k2 + 1) + v.z * (4 * k2 + 2) + v.w * (4 * k2 + 3);
            }
            lab[t] = (short)lv;
        }
        BAR2();
        const float* pb = p + (size_t)b * TT * DD;
        float s = 0.f;
        for (int t = idx; t < L; t += 128) {
            int lt = lab[t];
            s += pb[(size_t)t * DD + lt];
            if (t < L - 1) s += trans[lt * DD + lab[t + 1]];
        }
        #pragma unroll
        for (int ss = 16; ss >= 1; ss >>= 1) s += __shfl_xor_sync(0xffffffffu, s, ss);
        if (l == 0) sred[w - 4] = s;
    } else {
        // =========== recursion warps: serial forward chain ===========
        const float* pb = p + (size_t)b * TT * DD;

        // t = 0 prologue
        if (h == 0) ubuf[0][j] = __expf(pb[j]);

        float pf[8], exs[8];
        #pragma unroll
        for (int k2 = 0; k2 < 8; k2++) pf[k2] = 0.f;
        if (h == 0) {
            #pragma unroll
            for (int k2 = 0; k2 < 8; k2++)
                if (1 + k2 < L) pf[k2] = pb[(size_t)(1 + k2) * DD + j];
        }
        float Spend = 1.f;     // pending renorm scale (applied at next block start)
        int base = 1;
        BAR1();

        // ---- full blocks of 8 steps ----
        while (base + 7 <= L - 1) {
            #pragma unroll
            for (int k2 = 0; k2 < 8; k2++) exs[k2] = __expf(pf[k2]);
            // fold pending renorm into exs[0]; account logz (off critical path)
            exs[0] *= __fdividef(1.f, Spend);
            logz += __logf(Spend);
            // burst-prefetch next block
            if (h == 0) {
                #pragma unroll
                for (int k2 = 0; k2 < 8; k2++) {
                    int t2 = base + 8 + k2;
                    pf[k2] = (t2 < L) ? pb[(size_t)t2 * DD + j] : 0.f;
                }
            }

            #pragma unroll
            for (int k = 0; k < 8; k++) {
                const int t  = base + k;
                const int wb = t & 1, rb = wb ^ 1;
                const ulonglong2* ub =
                    reinterpret_cast<const ulonglong2*>(&ubuf[rb][h * 32]);
                ull a0 = 0, a1 = 0, a2 = 0, a3 = 0, ss0 = 0, ss1 = 0;
                #pragma unroll
                for (int q = 0; q < 4; q++) {
                    ulonglong2 u01 = ub[2 * q];
                    ulonglong2 u23 = ub[2 * q + 1];
                    FMA2(a0, u01.x, col2[4 * q + 0], a0);
                    FMA2(a1, u01.y, col2[4 * q + 1], a1);
                    FMA2(a2, u23.x, col2[4 * q + 2], a2);
                    FMA2(a3, u23.y, col2[4 * q + 3], a3);
                    if (k == 7) {   // renorm sum from loaded u_{base+6}, off acc chain
                        ADD2(ss0, ss0, u01.x); ADD2(ss0, ss0, u23.x);
                        ADD2(ss1, ss1, u01.y); ADD2(ss1, ss1, u23.y);
                    }
                }
                ADD2(a0, a0, a1); ADD2(a2, a2, a3); ADD2(a0, a0, a2);
                float lo, hi; UNPACK2(lo, hi, a0);
                float acc = lo + hi;
                acc += __shfl_xor_sync(0xffffffffu, acc, 16);
                if (h == 0) ubuf[wb][j] = exs[k] * acc;
                if (k == 7) {
                    ADD2(ss0, ss0, ss1);
                    float slo, shi; UNPACK2(slo, shi, ss0);
                    float Sh = slo + shi;              // sum over my i-half
                    Sh += __shfl_xor_sync(0xffffffffu, Sh, 16);
                    Spend = Sh;
                }
                BAR1();
            }
            base += 8;
        }

        // ---- remainder steps (pf already prefetched for this range) ----
        if (base <= L - 1) {
            const float rinvr = __fdividef(1.f, Spend);
            logz += __logf(Spend);
            for (int t = base; t <= L - 1; t++) {
                float ex = 0.f;
                if (h == 0) {
                    ex = __expf(pf[t - base]);
                    if (t == base) ex *= rinvr;
                }
                const int wb = t & 1, rb = wb ^ 1;
                const ulonglong2* ub =
                    reinterpret_cast<const ulonglong2*>(&ubuf[rb][h * 32]);
                ull a0 = 0, a1 = 0, a2 = 0, a3 = 0;
                #pragma unroll
                for (int q = 0; q < 4; q++) {
                    ulonglong2 u01 = ub[2 * q];
                    ulonglong2 u23 = ub[2 * q + 1];
                    FMA2(a0, u01.x, col2[4 * q + 0], a0);
                    FMA2(a1, u01.y, col2[4 * q + 1], a1);
                    FMA2(a2, u23.x, col2[4 * q + 2], a2);
                    FMA2(a3, u23.y, col2[4 * q + 3], a3);
                }
                ADD2(a0, a0, a1); ADD2(a2, a2, a3); ADD2(a0, a0, a2);
                float lo, hi; UNPACK2(lo, hi, a0);
                float acc = lo + hi;
                acc += __shfl_xor_sync(0xffffffffu, acc, 16);
                if (h == 0) ubuf[wb][j] = ex * acc;
                BAR1();
            }
        }
    }
    __syncthreads();

    // =========== epilogue: logZ + combine (warp 0, a recursion warp) ===========
    if (tid < 32) {
        const int fb = (L - 1) & 1;
        const float2* uf = reinterpret_cast<const float2*>(ubuf[fb]);
        float2 v = uf[tid];
        float sf = v.x + v.y;
        #pragma unroll
        for (int s = 16; s >= 1; s >>= 1) sf += __shfl_xor_sync(0xffffffffu, sf, s);
        if (tid == 0) {
            float s12 = sred[0] + sred[1] + sred[2] + sred[3];
            out[b] = logz + __logf(sf) - s12;
        }
    }
}

extern "C" void kernel_launch(void* const* d_in, const int* in_sizes, int n_in,
                              void* d_out, int out_size) {
    const float* p     = (const float*)d_in[0];
    const int*   y     = (const int*)d_in[1];
    const int*   mask  = (const int*)d_in[2];
    const float* trans = (const float*)d_in[3];
    float* out = (float*)d_out;
    (void)in_sizes; (void)n_in; (void)out_size;
    crf_fused<<<256, 256>>>(p, y, mask, trans, out);
}